// round 1
// baseline (speedup 1.0000x reference)
#include <cuda_runtime.h>

#define HH 64
#define WW 64
#define HWSZ 4096
#define CCH 64

// Scratch (allocation-free rule: __device__ globals)
__device__ float g_off[2 * 98 * HWSZ];   // max offsets buffer (B,2K,H,W)
__device__ float g_t0 [2 * CCH * HWSZ];  // intermediate (B,64,H,W)
__device__ float g_t1 [2 * CCH * HWSZ];  // intermediate (B,64,H,W)

// ---------------------------------------------------------------------------
// Offset conv: out[b,o,h,w] = bias[o] + sum_{c,i,j} src[b,c+coff,h+i*DIL-PAD,w+j*DIL-PAD]*wv[o,c,i,j]
// Block: 64 threads = one output row; each block does 2 output channels.
// Weights for the 2 output channels staged in shared memory (broadcast LDS).
// ---------------------------------------------------------------------------
template<int K, int DIL, int PAD>
__global__ void offconv_kernel(const float* __restrict__ src, int srcC, int coff,
                               const float* __restrict__ wv,
                               const float* __restrict__ bias,
                               float* __restrict__ out, int O)
{
    constexpr int KK = K * K;
    extern __shared__ float smw[];      // [2][64][KK]

    const int w  = threadIdx.x;
    const int h  = blockIdx.x;
    const int o0 = blockIdx.y * 2;
    const int b  = blockIdx.z;

    // Cooperative load of weights for o0, o0+1 (contiguous region in wv).
    const int nw = 2 * CCH * KK;
    const float* wsrc = wv + (size_t)o0 * CCH * KK;
    for (int idx = w; idx < nw; idx += 64) smw[idx] = wsrc[idx];
    __syncthreads();

    const float* srcb = src + ((size_t)b * srcC + coff) * HWSZ;
    float acc0 = bias[o0];
    float acc1 = bias[o0 + 1];

    for (int c = 0; c < CCH; ++c) {
        const float* xc = srcb + c * HWSZ;
        const float* w0 = smw + c * KK;
        const float* w1 = smw + (CCH + c) * KK;
        #pragma unroll
        for (int i = 0; i < K; ++i) {
            const int yy = h + i * DIL - PAD;
            if (yy < 0 || yy >= HH) continue;
            const float* xr = xc + yy * WW;
            float xt[K];
            #pragma unroll
            for (int j = 0; j < K; ++j) {
                const int xx = w + j * DIL - PAD;
                xt[j] = (xx >= 0 && xx < WW) ? xr[xx] : 0.f;
            }
            #pragma unroll
            for (int j = 0; j < K; ++j) {
                acc0 = fmaf(xt[j], w0[i * K + j], acc0);
                acc1 = fmaf(xt[j], w1[i * K + j], acc1);
            }
        }
    }
    float* ob = out + ((size_t)b * O + o0) * HWSZ + h * WW + w;
    ob[0]    = acc0;
    ob[HWSZ] = acc1;
}

// ---------------------------------------------------------------------------
// Deformable depthwise conv (bilinear sampling, zero padding outside).
// Thread per (b,c,h,w); offsets shared across channels (broadcast reads).
// ---------------------------------------------------------------------------
template<int KS, int DIL, int PAD>
__global__ void deform_kernel(const float* __restrict__ src, int srcC, int coff,
                              const float* __restrict__ off,
                              const float* __restrict__ dw,
                              float* __restrict__ out)
{
    constexpr int K = KS * KS;
    const int w = threadIdx.x;
    const int h = blockIdx.x;
    const int c = blockIdx.y;
    const int b = blockIdx.z;

    const float* xb = src + ((size_t)b * srcC + coff + c) * HWSZ;
    const float* ob = off + (size_t)b * (2 * K) * HWSZ + h * WW + w;
    const float* wc = dw + c * K;

    float acc = 0.f;
    #pragma unroll 1
    for (int kidx = 0; kidx < K; ++kidx) {
        const float oy = ob[(2 * kidx)     * HWSZ];
        const float ox = ob[(2 * kidx + 1) * HWSZ];
        const float py = oy + (float)(h - PAD + (kidx / KS) * DIL);
        const float px = ox + (float)(w - PAD + (kidx % KS) * DIL);
        const float y0f = floorf(py);
        const float x0f = floorf(px);
        const int   y0  = (int)y0f;
        const int   x0  = (int)x0f;
        const float ly  = py - y0f;
        const float lx  = px - x0f;
        const float hy  = 1.f - ly;
        const float hx  = 1.f - lx;

        const bool yv0 = (y0 >= 0)     && (y0 < HH);
        const bool yv1 = (y0 + 1 >= 0) && (y0 + 1 < HH);
        const bool xv0 = (x0 >= 0)     && (x0 < WW);
        const bool xv1 = (x0 + 1 >= 0) && (x0 + 1 < WW);

        const int yc0 = min(max(y0, 0), HH - 1);
        const int yc1 = min(max(y0 + 1, 0), HH - 1);
        const int xc0 = min(max(x0, 0), WW - 1);
        const int xc1 = min(max(x0 + 1, 0), WW - 1);

        const float v00 = (yv0 && xv0) ? xb[yc0 * WW + xc0] : 0.f;
        const float v01 = (yv0 && xv1) ? xb[yc0 * WW + xc1] : 0.f;
        const float v10 = (yv1 && xv0) ? xb[yc1 * WW + xc0] : 0.f;
        const float v11 = (yv1 && xv1) ? xb[yc1 * WW + xc1] : 0.f;

        const float val = v00 * hy * hx + v01 * hy * lx
                        + v10 * ly * hx + v11 * ly * lx;
        acc = fmaf(val, wc[kidx], acc);
    }
    out[((size_t)b * CCH + c) * HWSZ + h * WW + w] = acc;
}

// ---------------------------------------------------------------------------
// 1x1 conv fused with final gating:  d_out[b, xcoff+o, h, w] =
//   (bias[o] + sum_c in[b,c,h,w] * wv[o,c]) * x[b, xcoff+o, h, w]
// ---------------------------------------------------------------------------
__global__ void conv1x1_gate_kernel(const float* __restrict__ in,
                                    const float* __restrict__ wv,
                                    const float* __restrict__ bias,
                                    const float* __restrict__ x,
                                    int xcoff, float* __restrict__ out)
{
    const int w = threadIdx.x;
    const int h = blockIdx.x;
    const int o = blockIdx.y;
    const int b = blockIdx.z;

    float acc = bias[o];
    const float* ib = in + (size_t)b * CCH * HWSZ + h * WW + w;
    const float* wo = wv + o * CCH;
    #pragma unroll
    for (int c = 0; c < CCH; ++c)
        acc = fmaf(ib[c * HWSZ], wo[c], acc);

    const size_t oi = ((size_t)b * 128 + xcoff + o) * HWSZ + h * WW + w;
    out[oi] = acc * x[oi];
}

// ---------------------------------------------------------------------------
extern "C" void kernel_launch(void* const* d_in, const int* in_sizes, int n_in,
                              void* d_out, int out_size)
{
    const float* x          = (const float*)d_in[0];
    const float* cv0_off_w  = (const float*)d_in[1];
    const float* cv0_off_b  = (const float*)d_in[2];
    const float* cv0_w      = (const float*)d_in[3];
    const float* cvs_off_w  = (const float*)d_in[4];
    const float* cvs_off_b  = (const float*)d_in[5];
    const float* cvs_w      = (const float*)d_in[6];
    const float* c0_off_w   = (const float*)d_in[7];
    const float* c0_off_b   = (const float*)d_in[8];
    const float* c0_w       = (const float*)d_in[9];
    const float* cs_off_w   = (const float*)d_in[10];
    const float* cs_off_b   = (const float*)d_in[11];
    const float* cs_w       = (const float*)d_in[12];
    const float* conv1_w    = (const float*)d_in[13];
    const float* conv1_b    = (const float*)d_in[14];
    const float* conv2_w    = (const float*)d_in[15];
    const float* conv2_b    = (const float*)d_in[16];
    float* out = (float*)d_out;

    float *off, *t0, *t1;
    cudaGetSymbolAddress((void**)&off, g_off);
    cudaGetSymbolAddress((void**)&t0,  g_t0);
    cudaGetSymbolAddress((void**)&t1,  g_t1);

    dim3 blk(64);

    // ---- Branch 0: channels [0,64) ----
    offconv_kernel<3,1,1><<<dim3(64, 9, 2),  blk, 2*64*9*4 >>>(x, 128, 0, cv0_off_w, cv0_off_b, off, 18);
    deform_kernel <3,1,1><<<dim3(64, 64, 2), blk>>>(x, 128, 0, off, cv0_w, t0);
    offconv_kernel<5,3,6><<<dim3(64, 25, 2), blk, 2*64*25*4>>>(t0, 64, 0, cvs_off_w, cvs_off_b, off, 50);
    deform_kernel <5,3,6><<<dim3(64, 64, 2), blk>>>(t0, 64, 0, off, cvs_w, t1);
    conv1x1_gate_kernel<<<dim3(64, 64, 2), blk>>>(t1, conv1_w, conv1_b, x, 0, out);

    // ---- Branch 1: channels [64,128) ----
    offconv_kernel<5,1,2><<<dim3(64, 25, 2), blk, 2*64*25*4>>>(x, 128, 64, c0_off_w, c0_off_b, off, 50);
    deform_kernel <5,1,2><<<dim3(64, 64, 2), blk>>>(x, 128, 64, off, c0_w, t0);
    offconv_kernel<7,3,9><<<dim3(64, 49, 2), blk, 2*64*49*4>>>(t0, 64, 0, cs_off_w, cs_off_b, off, 98);
    deform_kernel <7,3,9><<<dim3(64, 64, 2), blk>>>(t0, 64, 0, off, cs_w, t1);
    conv1x1_gate_kernel<<<dim3(64, 64, 2), blk>>>(t1, conv2_w, conv2_b, x, 64, out);
}

// round 2
// speedup vs baseline: 1.6161x; 1.6161x over previous
#include <cuda_runtime.h>

#define HH 64
#define WW 64
#define HWSZ 4096
#define CCH 64

// ---- device scratch (allocation-free rule) ----
__device__ float g_off [2 * 98 * HWSZ];          // offsets (B, 2K, H, W)
__device__ float g_t0  [2 * CCH * HWSZ];         // intermediate
__device__ float g_t1  [2 * CCH * HWSZ];         // intermediate
__device__ float g_part[8 * 2 * 128 * HWSZ];     // split-C partial sums [sp][b][128][4096]
__device__ float g_wt  [524288];                 // transposed weights, 4 sets packed

// ---------------------------------------------------------------------------
// Weight transpose: wv[O][64][K][K]  ->  wt[tap][O], tap = c*K*K + i*K + j
// ---------------------------------------------------------------------------
__global__ void wtrans_kernel(const float* __restrict__ wv, int O, int taps,
                              float* __restrict__ wt)
{
    int idx = blockIdx.x * 256 + threadIdx.x;
    if (idx < O * taps) {
        int o = idx / taps;
        int t = idx - o * taps;
        wt[(size_t)t * O + o] = wv[idx];
    }
}

// ---------------------------------------------------------------------------
// Offset conv as implicit GEMM with register tiling.
// Block: 256 thr. Tile: 32 out-ch x (4 rows x 64 cols). Per-thread: 8o x 4p.
// grid = (16 hblk, ceil(O/32), 2*ns);  c-range split over ns for occupancy.
// Writes partial sums (no bias) to part[sp][b][o][pix].
// ---------------------------------------------------------------------------
template<int K, int DIL, int PAD>
__global__ void offconv_gemm(const float* __restrict__ src, int srcC, int coff,
                             const float* __restrict__ wt, int O, int ns,
                             float* __restrict__ part)
{
    constexpr int KK   = K * K;
    constexpr int WPAD = 64 + 2 * PAD;

    __shared__ float XS[4][WPAD];
    __shared__ float WS[K][32];

    const int tid  = threadIdx.x;
    const int lane = tid & 63;
    const int og   = tid >> 6;            // 0..3
    const int h0   = blockIdx.x * 4;
    const int o0   = blockIdx.y * 32;
    const int b    = blockIdx.z / ns;
    const int sp   = blockIdx.z % ns;
    const int cchunk = CCH / ns;
    const int cbeg = sp * cchunk;
    const int cend = cbeg + cchunk;

    float acc[8][4];
    #pragma unroll
    for (int oc = 0; oc < 8; ++oc)
        #pragma unroll
        for (int r = 0; r < 4; ++r) acc[oc][r] = 0.f;

    for (int c = cbeg; c < cend; ++c) {
        const float* sc = src + (((size_t)b * srcC + coff + c) << 12);
        const float* wc = wt + (size_t)c * KK * O;
        #pragma unroll 1
        for (int i = 0; i < K; ++i) {
            __syncthreads();
            // stage padded x rows for this (c, i)
            const int yb = h0 + i * DIL - PAD;
            for (int idx = tid; idx < 4 * WPAD; idx += 256) {
                const int r   = idx / WPAD;
                const int s   = idx - r * WPAD;
                const int yy  = yb + r;
                const int col = s - PAD;
                float v = 0.f;
                if ((unsigned)yy < 64u && (unsigned)col < 64u)
                    v = sc[yy * 64 + col];
                XS[r][s] = v;
            }
            // stage weights for (c, i): WS[j][oc], coalesced from tap-major wt
            if (tid < K * 32) {
                const int j  = tid >> 5;
                const int oc = tid & 31;
                const int o  = o0 + oc;
                WS[j][oc] = (o < O) ? wc[(i * K + j) * O + o] : 0.f;
            }
            __syncthreads();

            #pragma unroll
            for (int j = 0; j < K; ++j) {
                const float4 wA = *(const float4*)&WS[j][og * 8];
                const float4 wB = *(const float4*)&WS[j][og * 8 + 4];
                float xv[4];
                #pragma unroll
                for (int r = 0; r < 4; ++r) xv[r] = XS[r][lane + j * DIL];
                #pragma unroll
                for (int r = 0; r < 4; ++r) {
                    acc[0][r] = fmaf(wA.x, xv[r], acc[0][r]);
                    acc[1][r] = fmaf(wA.y, xv[r], acc[1][r]);
                    acc[2][r] = fmaf(wA.z, xv[r], acc[2][r]);
                    acc[3][r] = fmaf(wA.w, xv[r], acc[3][r]);
                    acc[4][r] = fmaf(wB.x, xv[r], acc[4][r]);
                    acc[5][r] = fmaf(wB.y, xv[r], acc[5][r]);
                    acc[6][r] = fmaf(wB.z, xv[r], acc[6][r]);
                    acc[7][r] = fmaf(wB.w, xv[r], acc[7][r]);
                }
            }
        }
    }

    // store partial tile
    float* pb = part + (((size_t)sp * 2 + b) * 128) * HWSZ;
    #pragma unroll
    for (int oc = 0; oc < 8; ++oc) {
        const int o = o0 + og * 8 + oc;
        if (o < O) {
            #pragma unroll
            for (int r = 0; r < 4; ++r)
                pb[(size_t)o * HWSZ + (h0 + r) * 64 + lane] = acc[oc][r];
        }
    }
}

// combine: out[b,o,p] = bias[o] + sum_sp part[sp][b][o][p]
__global__ void combine_kernel(const float* __restrict__ part,
                               const float* __restrict__ bias,
                               int O, int ns, float* __restrict__ out)
{
    const int p = blockIdx.x * 256 + threadIdx.x;
    const int o = blockIdx.y;
    const int b = blockIdx.z;
    float s = bias[o];
    for (int sp = 0; sp < ns; ++sp)
        s += part[(((size_t)sp * 2 + b) * 128 + o) * HWSZ + p];
    out[((size_t)b * O + o) * HWSZ + p] = s;
}

// ---------------------------------------------------------------------------
// Deformable depthwise conv (bilinear sampling, zero padding outside).
// ---------------------------------------------------------------------------
template<int KS, int DIL, int PAD>
__global__ void deform_kernel(const float* __restrict__ src, int srcC, int coff,
                              const float* __restrict__ off,
                              const float* __restrict__ dw,
                              float* __restrict__ out)
{
    constexpr int K = KS * KS;
    const int w = threadIdx.x;
    const int h = blockIdx.x;
    const int c = blockIdx.y;
    const int b = blockIdx.z;

    const float* xb = src + ((size_t)b * srcC + coff + c) * HWSZ;
    const float* ob = off + (size_t)b * (2 * K) * HWSZ + h * WW + w;
    const float* wc = dw + c * K;

    float acc = 0.f;
    #pragma unroll 1
    for (int kidx = 0; kidx < K; ++kidx) {
        const float oy = ob[(2 * kidx)     * HWSZ];
        const float ox = ob[(2 * kidx + 1) * HWSZ];
        const float py = oy + (float)(h - PAD + (kidx / KS) * DIL);
        const float px = ox + (float)(w - PAD + (kidx % KS) * DIL);
        const int   y0 = __float2int_rd(py);
        const int   x0 = __float2int_rd(px);
        const float ly = py - (float)y0;
        const float lx = px - (float)x0;
        const float hy = 1.f - ly;
        const float hx = 1.f - lx;

        const bool yv0 = (unsigned)y0       < (unsigned)HH;
        const bool yv1 = (unsigned)(y0 + 1) < (unsigned)HH;
        const bool xv0 = (unsigned)x0       < (unsigned)WW;
        const bool xv1 = (unsigned)(x0 + 1) < (unsigned)WW;

        const int yc0 = min(max(y0, 0), HH - 1);
        const int yc1 = min(y0 + 1, HH - 1);
        const int xc0 = min(max(x0, 0), WW - 1);
        const int xc1 = min(x0 + 1, WW - 1);

        const float v00 = (yv0 && xv0) ? xb[yc0 * WW + xc0] : 0.f;
        const float v01 = (yv0 && xv1) ? xb[yc0 * WW + xc1] : 0.f;
        const float v10 = (yv1 && xv0) ? xb[yc1 * WW + xc0] : 0.f;
        const float v11 = (yv1 && xv1) ? xb[yc1 * WW + xc1] : 0.f;

        const float val = (v00 * hx + v01 * lx) * hy
                        + (v10 * hx + v11 * lx) * ly;
        acc = fmaf(val, wc[kidx], acc);
    }
    out[((size_t)b * CCH + c) * HWSZ + h * WW + w] = acc;
}

// ---------------------------------------------------------------------------
// 1x1 conv fused with final gating
// ---------------------------------------------------------------------------
__global__ void conv1x1_gate_kernel(const float* __restrict__ in,
                                    const float* __restrict__ wv,
                                    const float* __restrict__ bias,
                                    const float* __restrict__ x,
                                    int xcoff, float* __restrict__ out)
{
    const int w = threadIdx.x;
    const int h = blockIdx.x;
    const int o = blockIdx.y;
    const int b = blockIdx.z;

    float acc = bias[o];
    const float* ib = in + (size_t)b * CCH * HWSZ + h * WW + w;
    const float* wo = wv + o * CCH;
    #pragma unroll
    for (int c = 0; c < CCH; ++c)
        acc = fmaf(ib[c * HWSZ], wo[c], acc);

    const size_t oi = ((size_t)b * 128 + xcoff + o) * HWSZ + h * WW + w;
    out[oi] = acc * x[oi];
}

// ---------------------------------------------------------------------------
extern "C" void kernel_launch(void* const* d_in, const int* in_sizes, int n_in,
                              void* d_out, int out_size)
{
    const float* x          = (const float*)d_in[0];
    const float* cv0_off_w  = (const float*)d_in[1];
    const float* cv0_off_b  = (const float*)d_in[2];
    const float* cv0_w      = (const float*)d_in[3];
    const float* cvs_off_w  = (const float*)d_in[4];
    const float* cvs_off_b  = (const float*)d_in[5];
    const float* cvs_w      = (const float*)d_in[6];
    const float* c0_off_w   = (const float*)d_in[7];
    const float* c0_off_b   = (const float*)d_in[8];
    const float* c0_w       = (const float*)d_in[9];
    const float* cs_off_w   = (const float*)d_in[10];
    const float* cs_off_b   = (const float*)d_in[11];
    const float* cs_w       = (const float*)d_in[12];
    const float* conv1_w    = (const float*)d_in[13];
    const float* conv1_b    = (const float*)d_in[14];
    const float* conv2_w    = (const float*)d_in[15];
    const float* conv2_b    = (const float*)d_in[16];
    float* out = (float*)d_out;

    float *off, *t0, *t1, *part, *wt;
    cudaGetSymbolAddress((void**)&off,  g_off);
    cudaGetSymbolAddress((void**)&t0,   g_t0);
    cudaGetSymbolAddress((void**)&t1,   g_t1);
    cudaGetSymbolAddress((void**)&part, g_part);
    cudaGetSymbolAddress((void**)&wt,   g_wt);

    // packed transposed-weight offsets
    const int taps3 = 64 * 9,  taps5 = 64 * 25, taps7 = 64 * 49;
    float* wt_cv0 = wt;                         // 18*576   = 10368
    float* wt_cvs = wt_cv0 + 18 * taps3;        // 50*1600  = 80000
    float* wt_c0  = wt_cvs + 50 * taps5;        // 50*1600  = 80000
    float* wt_cs  = wt_c0  + 50 * taps5;        // 98*3136  = 307328

    dim3 b64(64), b256(256);

    // weight transposes (independent, run up-front)
    wtrans_kernel<<<(18 * taps3 + 255) / 256, b256>>>(cv0_off_w, 18, taps3, wt_cv0);
    wtrans_kernel<<<(50 * taps5 + 255) / 256, b256>>>(cvs_off_w, 50, taps5, wt_cvs);
    wtrans_kernel<<<(50 * taps5 + 255) / 256, b256>>>(c0_off_w,  50, taps5, wt_c0);
    wtrans_kernel<<<(98 * taps7 + 255) / 256, b256>>>(cs_off_w,  98, taps7, wt_cs);

    // ---- Branch 0: channels [0,64) ----
    offconv_gemm<3,1,1><<<dim3(16, 1, 2 * 8), b256>>>(x, 128, 0, wt_cv0, 18, 8, part);
    combine_kernel<<<dim3(16, 18, 2), b256>>>(part, cv0_off_b, 18, 8, off);
    deform_kernel<3,1,1><<<dim3(64, 64, 2), b64>>>(x, 128, 0, off, cv0_w, t0);

    offconv_gemm<5,3,6><<<dim3(16, 2, 2 * 4), b256>>>(t0, 64, 0, wt_cvs, 50, 4, part);
    combine_kernel<<<dim3(16, 50, 2), b256>>>(part, cvs_off_b, 50, 4, off);
    deform_kernel<5,3,6><<<dim3(64, 64, 2), b64>>>(t0, 64, 0, off, cvs_w, t1);

    conv1x1_gate_kernel<<<dim3(64, 64, 2), b64>>>(t1, conv1_w, conv1_b, x, 0, out);

    // ---- Branch 1: channels [64,128) ----
    offconv_gemm<5,1,2><<<dim3(16, 2, 2 * 4), b256>>>(x, 128, 64, wt_c0, 50, 4, part);
    combine_kernel<<<dim3(16, 50, 2), b256>>>(part, c0_off_b, 50, 4, off);
    deform_kernel<5,1,2><<<dim3(64, 64, 2), b64>>>(x, 128, 64, off, c0_w, t0);

    offconv_gemm<7,3,9><<<dim3(16, 4, 2 * 2), b256>>>(t0, 64, 0, wt_cs, 98, 2, part);
    combine_kernel<<<dim3(16, 98, 2), b256>>>(part, cs_off_b, 98, 2, off);
    deform_kernel<7,3,9><<<dim3(64, 64, 2), b64>>>(t0, 64, 0, off, cs_w, t1);

    conv1x1_gate_kernel<<<dim3(64, 64, 2), b64>>>(t1, conv2_w, conv2_b, x, 64, out);
}

// round 3
// speedup vs baseline: 2.1122x; 1.3070x over previous
#include <cuda_runtime.h>

#define HH 64
#define WW 64
#define HWSZ 4096
#define CCH 64

// ---- device scratch (allocation-free rule) ----
__device__ float g_off [2 * 98 * HWSZ];          // offsets (B, 2K, H, W)
__device__ float g_t0  [2 * CCH * HWSZ];         // intermediate
__device__ float g_t1  [2 * CCH * HWSZ];         // intermediate
__device__ float g_part[8 * 2 * 128 * HWSZ];     // split-C partials [sp][b][128][4096]
__device__ float g_wt  [524288];                 // transposed weights, 4 sets packed

// ---- packed f32x2 helpers ----
__device__ __forceinline__ unsigned long long pk2(float lo, float hi) {
    unsigned long long r;
    asm("mov.b64 %0, {%1, %2};" : "=l"(r) : "f"(lo), "f"(hi));
    return r;
}
__device__ __forceinline__ void fma2(unsigned long long& d, unsigned long long a,
                                     unsigned long long b) {
    asm("fma.rn.f32x2 %0, %1, %2, %3;" : "=l"(d) : "l"(a), "l"(b), "l"(d));
}
__device__ __forceinline__ void unpk2(unsigned long long v, float& lo, float& hi) {
    asm("mov.b64 {%0, %1}, %2;" : "=f"(lo), "=f"(hi) : "l"(v));
}
__device__ __forceinline__ unsigned long long mul2(unsigned long long a,
                                                   unsigned long long b) {
    unsigned long long r;
    asm("mul.rn.f32x2 %0, %1, %2;" : "=l"(r) : "l"(a), "l"(b));
    return r;
}

// ---------------------------------------------------------------------------
// Fused weight transpose for all 4 offset convs: wv[O][64][K][K] -> wt[tap][O]
// ---------------------------------------------------------------------------
__global__ void wtrans_all(const float* __restrict__ w0, // 18 x 576
                           const float* __restrict__ w1, // 50 x 1600
                           const float* __restrict__ w2, // 50 x 1600
                           const float* __restrict__ w3, // 98 x 3136
                           float* __restrict__ wt)
{
    int idx = blockIdx.x * 256 + threadIdx.x;
    const int n0 = 18 * 576, n1 = 50 * 1600, n2 = 50 * 1600, n3 = 98 * 3136;
    const float* src; int O, taps; float* dst;
    if (idx < n0)                { src = w0; O = 18; taps = 576;  dst = wt; }
    else if ((idx -= n0) < n1)   { src = w1; O = 50; taps = 1600; dst = wt + n0; }
    else if ((idx -= n1) < n2)   { src = w2; O = 50; taps = 1600; dst = wt + n0 + n1; }
    else if ((idx -= n2) < n3)   { src = w3; O = 98; taps = 3136; dst = wt + n0 + n1 + n2; }
    else return;
    int o = idx / taps;
    int t = idx - o * taps;
    dst[(size_t)t * O + o] = src[idx];
}

// ---------------------------------------------------------------------------
// Offset conv as implicit GEMM, f32x2 packed FMA.
// Block 256 thr; tile 32 oc x (4 rows x 64 cols); per-thread 8 oc x 2 f32x2.
// grid = (16 hblk, ceil(O/32), 2*ns). Partial sums (no bias) to part.
// ---------------------------------------------------------------------------
template<int K, int DIL, int PAD>
__global__ void offconv_gemm(const float* __restrict__ src, int srcC, int coff,
                             const float* __restrict__ wt, int O, int ns,
                             float* __restrict__ part)
{
    constexpr int KK     = K * K;
    constexpr int WPAD   = 64 + 2 * PAD;
    constexpr int ROWS_X = 4 + (K - 1) * DIL;

    __shared__ float  XS[ROWS_X][WPAD];
    __shared__ float2 WS2[KK][32];          // (w, w) duplicated

    const int tid  = threadIdx.x;
    const int lane = tid & 63;
    const int og   = tid >> 6;              // 0..3
    const int h0   = blockIdx.x * 4;
    const int o0   = blockIdx.y * 32;
    const int b    = blockIdx.z / ns;
    const int sp   = blockIdx.z % ns;
    const int cchunk = CCH / ns;
    const int cbeg = sp * cchunk;
    const int cend = cbeg + cchunk;

    unsigned long long acc[8][2];
    #pragma unroll
    for (int oc = 0; oc < 8; ++oc) { acc[oc][0] = 0ull; acc[oc][1] = 0ull; }

    for (int c = cbeg; c < cend; ++c) {
        const float* sc = src + (((size_t)b * srcC + coff + c) << 12);
        const float* wc = wt + (size_t)c * KK * O;
        __syncthreads();
        // stage padded x rows [h0-PAD, h0+3+(K-1)*DIL-PAD]
        for (int idx = tid; idx < ROWS_X * WPAD; idx += 256) {
            const int rr  = idx / WPAD;
            const int s   = idx - rr * WPAD;
            const int yy  = h0 - PAD + rr;
            const int col = s - PAD;
            float v = 0.f;
            if ((unsigned)yy < 64u && (unsigned)col < 64u) v = sc[yy * 64 + col];
            XS[rr][s] = v;
        }
        // stage duplicated weights for this c
        for (int idx = tid; idx < KK * 32; idx += 256) {
            const int tap = idx >> 5;
            const int oc  = idx & 31;
            const int o   = o0 + oc;
            const float w = (o < O) ? wc[tap * O + o] : 0.f;
            WS2[tap][oc] = make_float2(w, w);
        }
        __syncthreads();

        #pragma unroll 1
        for (int i = 0; i < K; ++i) {
            const int ri = i * DIL;
            #pragma unroll
            for (int j = 0; j < K; ++j) {
                const ulonglong2* wrow =
                    (const ulonglong2*)&WS2[i * K + j][og * 8];
                const ulonglong2 wq0 = wrow[0];
                const ulonglong2 wq1 = wrow[1];
                const ulonglong2 wq2 = wrow[2];
                const ulonglong2 wq3 = wrow[3];
                const int sx = lane + j * DIL;
                const unsigned long long xa = pk2(XS[ri + 0][sx], XS[ri + 1][sx]);
                const unsigned long long xb = pk2(XS[ri + 2][sx], XS[ri + 3][sx]);
                fma2(acc[0][0], wq0.x, xa);  fma2(acc[0][1], wq0.x, xb);
                fma2(acc[1][0], wq0.y, xa);  fma2(acc[1][1], wq0.y, xb);
                fma2(acc[2][0], wq1.x, xa);  fma2(acc[2][1], wq1.x, xb);
                fma2(acc[3][0], wq1.y, xa);  fma2(acc[3][1], wq1.y, xb);
                fma2(acc[4][0], wq2.x, xa);  fma2(acc[4][1], wq2.x, xb);
                fma2(acc[5][0], wq2.y, xa);  fma2(acc[5][1], wq2.y, xb);
                fma2(acc[6][0], wq3.x, xa);  fma2(acc[6][1], wq3.x, xb);
                fma2(acc[7][0], wq3.y, xa);  fma2(acc[7][1], wq3.y, xb);
            }
        }
    }

    float* pb = part + (((size_t)sp * 2 + b) * 128) * HWSZ;
    #pragma unroll
    for (int oc = 0; oc < 8; ++oc) {
        const int o = o0 + og * 8 + oc;
        if (o < O) {
            float r0, r1, r2, r3;
            unpk2(acc[oc][0], r0, r1);
            unpk2(acc[oc][1], r2, r3);
            float* po = pb + (size_t)o * HWSZ + h0 * 64 + lane;
            po[0]   = r0;
            po[64]  = r1;
            po[128] = r2;
            po[192] = r3;
        }
    }
}

// combine: out[b,o,p] = bias[o] + sum_sp part[sp][b][o][p]   (float4)
__global__ void combine_kernel(const float* __restrict__ part,
                               const float* __restrict__ bias,
                               int O, int ns, float* __restrict__ out)
{
    const int p = blockIdx.x * 256 + threadIdx.x;   // float4 index within 1024
    const int o = blockIdx.y;
    const int b = blockIdx.z;
    const float bs = bias[o];
    float4 s = make_float4(bs, bs, bs, bs);
    for (int sp = 0; sp < ns; ++sp) {
        const float4 v = ((const float4*)part)[(((size_t)sp * 2 + b) * 128 + o) * 1024 + p];
        s.x += v.x; s.y += v.y; s.z += v.z; s.w += v.w;
    }
    ((float4*)out)[((size_t)b * O + o) * 1024 + p] = s;
}

// ---------------------------------------------------------------------------
// Deformable depthwise conv: index math computed once per tap, applied to
// 8 channels. Always-load with clamped indices + validity-masked weights.
// Block 256 thr (4 rows x 64 cols); grid (16, 8 cgroups, 2).
// ---------------------------------------------------------------------------
template<int KS, int DIL, int PAD>
__global__ void deform_kernel(const float* __restrict__ src, int srcC, int coff,
                              const float* __restrict__ off,
                              const float* __restrict__ dw,
                              float* __restrict__ out)
{
    constexpr int K = KS * KS;
    __shared__ float sdw[8][K];

    const int tid = threadIdx.x;
    const int w   = tid & 63;
    const int r   = tid >> 6;
    const int h   = blockIdx.x * 4 + r;
    const int cg  = blockIdx.y;             // channel group of 8
    const int b   = blockIdx.z;

    for (int idx = tid; idx < 8 * K; idx += 256) {
        const int c = idx / K;
        const int k = idx - c * K;
        sdw[c][k] = dw[(cg * 8 + c) * K + k];
    }
    __syncthreads();

    const float* xb = src + ((size_t)b * srcC + coff + cg * 8) * HWSZ;
    const float* ob = off + (size_t)b * (2 * K) * HWSZ + h * WW + w;

    float acc[8];
    #pragma unroll
    for (int c = 0; c < 8; ++c) acc[c] = 0.f;

    #pragma unroll 1
    for (int kidx = 0; kidx < K; ++kidx) {
        const float oy = ob[(2 * kidx)     * HWSZ];
        const float ox = ob[(2 * kidx + 1) * HWSZ];
        const float py = oy + (float)(h - PAD + (kidx / KS) * DIL);
        const float px = ox + (float)(w - PAD + (kidx % KS) * DIL);
        const int   y0 = __float2int_rd(py);
        const int   x0 = __float2int_rd(px);
        const float ly = py - (float)y0;
        const float lx = px - (float)x0;
        const float hy = 1.f - ly;
        const float hx = 1.f - lx;

        const float m_y0 = ((unsigned)y0       < 64u) ? 1.f : 0.f;
        const float m_y1 = ((unsigned)(y0 + 1) < 64u) ? 1.f : 0.f;
        const float m_x0 = ((unsigned)x0       < 64u) ? 1.f : 0.f;
        const float m_x1 = ((unsigned)(x0 + 1) < 64u) ? 1.f : 0.f;

        const int yc0 = min(max(y0, 0), 63);
        const int yc1 = min(max(y0 + 1, 0), 63);
        const int xc0 = min(max(x0, 0), 63);
        const int xc1 = min(max(x0 + 1, 0), 63);

        const int i00 = yc0 * 64 + xc0;
        const int i01 = yc0 * 64 + xc1;
        const int i10 = yc1 * 64 + xc0;
        const int i11 = yc1 * 64 + xc1;

        const float w00 = hy * hx * (m_y0 * m_x0);
        const float w01 = hy * lx * (m_y0 * m_x1);
        const float w10 = ly * hx * (m_y1 * m_x0);
        const float w11 = ly * lx * (m_y1 * m_x1);

        #pragma unroll
        for (int c = 0; c < 8; ++c) {
            const float* xc = xb + c * HWSZ;
            float v = xc[i00] * w00;
            v = fmaf(xc[i01], w01, v);
            v = fmaf(xc[i10], w10, v);
            v = fmaf(xc[i11], w11, v);
            acc[c] = fmaf(v, sdw[c][kidx], acc[c]);
        }
    }

    #pragma unroll
    for (int c = 0; c < 8; ++c)
        out[((size_t)b * CCH + cg * 8 + c) * HWSZ + h * WW + w] = acc[c];
}

// ---------------------------------------------------------------------------
// 1x1 conv fused with gating, f32x2: each thread = 2 adjacent pixels.
// Block 256 thr (512 px = 8 rows); grid (8, 64, 2).
// ---------------------------------------------------------------------------
__global__ void conv1x1_gate_kernel(const float* __restrict__ in,
                                    const float* __restrict__ wv,
                                    const float* __restrict__ bias,
                                    const float* __restrict__ x,
                                    int xcoff, float* __restrict__ out)
{
    __shared__ float2 wdup[CCH];
    const int tid = threadIdx.x;
    const int o   = blockIdx.y;
    const int b   = blockIdx.z;
    const int px0 = blockIdx.x * 512 + tid * 2;

    if (tid < CCH) {
        const float wv_ = wv[o * CCH + tid];
        wdup[tid] = make_float2(wv_, wv_);
    }
    __syncthreads();

    const float bs = bias[o];
    unsigned long long acc = pk2(bs, bs);
    const char* ib = (const char*)(in + (size_t)b * CCH * HWSZ + px0);
    #pragma unroll
    for (int c = 0; c < CCH; ++c) {
        const unsigned long long iv = *(const unsigned long long*)(ib + (size_t)c * (HWSZ * 4));
        const unsigned long long wq = *(const unsigned long long*)&wdup[c];
        fma2(acc, wq, iv);
    }

    const size_t oi = ((size_t)b * 128 + xcoff + o) * HWSZ + px0;
    const unsigned long long xv = *(const unsigned long long*)(x + oi);
    *(unsigned long long*)(out + oi) = mul2(acc, xv);
}

// ---------------------------------------------------------------------------
extern "C" void kernel_launch(void* const* d_in, const int* in_sizes, int n_in,
                              void* d_out, int out_size)
{
    const float* x          = (const float*)d_in[0];
    const float* cv0_off_w  = (const float*)d_in[1];
    const float* cv0_off_b  = (const float*)d_in[2];
    const float* cv0_w      = (const float*)d_in[3];
    const float* cvs_off_w  = (const float*)d_in[4];
    const float* cvs_off_b  = (const float*)d_in[5];
    const float* cvs_w      = (const float*)d_in[6];
    const float* c0_off_w   = (const float*)d_in[7];
    const float* c0_off_b   = (const float*)d_in[8];
    const float* c0_w       = (const float*)d_in[9];
    const float* cs_off_w   = (const float*)d_in[10];
    const float* cs_off_b   = (const float*)d_in[11];
    const float* cs_w       = (const float*)d_in[12];
    const float* conv1_w    = (const float*)d_in[13];
    const float* conv1_b    = (const float*)d_in[14];
    const float* conv2_w    = (const float*)d_in[15];
    const float* conv2_b    = (const float*)d_in[16];
    float* out = (float*)d_out;

    float *off, *t0, *t1, *part, *wt;
    cudaGetSymbolAddress((void**)&off,  g_off);
    cudaGetSymbolAddress((void**)&t0,   g_t0);
    cudaGetSymbolAddress((void**)&t1,   g_t1);
    cudaGetSymbolAddress((void**)&part, g_part);
    cudaGetSymbolAddress((void**)&wt,   g_wt);

    const int taps3 = 576, taps5 = 1600, taps7 = 3136;
    float* wt_cv0 = wt;
    float* wt_cvs = wt_cv0 + 18 * taps3;
    float* wt_c0  = wt_cvs + 50 * taps5;
    float* wt_cs  = wt_c0  + 50 * taps5;

    dim3 b256(256);
    const int n_all = 18 * taps3 + 50 * taps5 + 50 * taps5 + 98 * taps7;
    wtrans_all<<<(n_all + 255) / 256, b256>>>(cv0_off_w, cvs_off_w, c0_off_w, cs_off_w, wt);

    // ---- Branch 0: channels [0,64) ----
    offconv_gemm<3,1,1><<<dim3(16, 1, 2 * 8), b256>>>(x, 128, 0, wt_cv0, 18, 8, part);
    combine_kernel<<<dim3(4, 18, 2), b256>>>(part, cv0_off_b, 18, 8, off);
    deform_kernel<3,1,1><<<dim3(16, 8, 2), b256>>>(x, 128, 0, off, cv0_w, t0);

    offconv_gemm<5,3,6><<<dim3(16, 2, 2 * 4), b256>>>(t0, 64, 0, wt_cvs, 50, 4, part);
    combine_kernel<<<dim3(4, 50, 2), b256>>>(part, cvs_off_b, 50, 4, off);
    deform_kernel<5,3,6><<<dim3(16, 8, 2), b256>>>(t0, 64, 0, off, cvs_w, t1);

    conv1x1_gate_kernel<<<dim3(8, 64, 2), b256>>>(t1, conv1_w, conv1_b, x, 0, out);

    // ---- Branch 1: channels [64,128) ----
    offconv_gemm<5,1,2><<<dim3(16, 2, 2 * 4), b256>>>(x, 128, 64, wt_c0, 50, 4, part);
    combine_kernel<<<dim3(4, 50, 2), b256>>>(part, c0_off_b, 50, 4, off);
    deform_kernel<5,1,2><<<dim3(16, 8, 2), b256>>>(x, 128, 64, off, c0_w, t0);

    offconv_gemm<7,3,9><<<dim3(16, 4, 2 * 2), b256>>>(t0, 64, 0, wt_cs, 98, 2, part);
    combine_kernel<<<dim3(4, 98, 2), b256>>>(part, cs_off_b, 98, 2, off);
    deform_kernel<7,3,9><<<dim3(16, 8, 2), b256>>>(t0, 64, 0, off, cs_w, t1);

    conv1x1_gate_kernel<<<dim3(8, 64, 2), b256>>>(t1, conv2_w, conv2_b, x, 64, out);
}

// round 4
// speedup vs baseline: 2.6112x; 1.2363x over previous
#include <cuda_runtime.h>

#define HH 64
#define WW 64
#define HWSZ 4096
#define CCH 64

// ---- device scratch (allocation-free rule) ----
__device__ float g_off [2 * 296 * HWSZ];         // offsets: branch0 @0 (<=100ch), branch1 @2*100*HWSZ (<=196ch)
__device__ float g_tmp [4 * CCH * 2 * HWSZ];     // t0a,t1a,t0b,t1b
__device__ float g_part[8 * 2 * 128 * HWSZ];     // split-C partials, split between branches
__device__ float g_wt  [524288];                 // transposed weights, 4 sets packed

// ---- packed f32x2 helpers ----
__device__ __forceinline__ unsigned long long pk2(float lo, float hi) {
    unsigned long long r;
    asm("mov.b64 %0, {%1, %2};" : "=l"(r) : "f"(lo), "f"(hi));
    return r;
}
__device__ __forceinline__ void fma2(unsigned long long& d, unsigned long long a,
                                     unsigned long long b) {
    asm("fma.rn.f32x2 %0, %1, %2, %3;" : "=l"(d) : "l"(a), "l"(b), "l"(d));
}
__device__ __forceinline__ void unpk2(unsigned long long v, float& lo, float& hi) {
    asm("mov.b64 {%0, %1}, %2;" : "=f"(lo), "=f"(hi) : "l"(v));
}
__device__ __forceinline__ unsigned long long mul2(unsigned long long a,
                                                   unsigned long long b) {
    unsigned long long r;
    asm("mul.rn.f32x2 %0, %1, %2;" : "=l"(r) : "l"(a), "l"(b));
    return r;
}

// ---------------------------------------------------------------------------
// Fused weight transpose for all 4 offset convs: wv[O][64][K][K] -> wt[tap][O]
// ---------------------------------------------------------------------------
__global__ void wtrans_all(const float* __restrict__ w0,
                           const float* __restrict__ w1,
                           const float* __restrict__ w2,
                           const float* __restrict__ w3,
                           float* __restrict__ wt)
{
    int idx = blockIdx.x * 256 + threadIdx.x;
    const int n0 = 18 * 576, n1 = 50 * 1600, n2 = 50 * 1600, n3 = 98 * 3136;
    const float* src; int O, taps; float* dst;
    if (idx < n0)                { src = w0; O = 18; taps = 576;  dst = wt; }
    else if ((idx -= n0) < n1)   { src = w1; O = 50; taps = 1600; dst = wt + n0; }
    else if ((idx -= n1) < n2)   { src = w2; O = 50; taps = 1600; dst = wt + n0 + n1; }
    else if ((idx -= n2) < n3)   { src = w3; O = 98; taps = 3136; dst = wt + n0 + n1 + n2; }
    else return;
    int o = idx / taps;
    int t = idx - o * taps;
    dst[(size_t)t * O + o] = src[idx];
}

// ---------------------------------------------------------------------------
// Offset conv as implicit GEMM, f32x2 packed FMA.
// Block 256 thr; tile 32 oc x (4 rows x 64 cols); per-thread 8 oc x 2 f32x2.
// grid = (16 hblk, ceil(O/32), 2*ns). Partials [sp][b][O][HWSZ] (no bias).
// ---------------------------------------------------------------------------
template<int K, int DIL, int PAD>
__global__ void offconv_gemm(const float* __restrict__ src, int srcC, int coff,
                             const float* __restrict__ wt, int O, int ns,
                             float* __restrict__ part)
{
    constexpr int KK     = K * K;
    constexpr int WPAD   = 64 + 2 * PAD;
    constexpr int ROWS_X = 4 + (K - 1) * DIL;

    __shared__ float  XS[ROWS_X][WPAD];
    __shared__ float2 WS2[KK][32];

    const int tid  = threadIdx.x;
    const int lane = tid & 63;
    const int og   = tid >> 6;
    const int h0   = blockIdx.x * 4;
    const int o0   = blockIdx.y * 32;
    const int b    = blockIdx.z / ns;
    const int sp   = blockIdx.z % ns;
    const int cchunk = CCH / ns;
    const int cbeg = sp * cchunk;
    const int cend = cbeg + cchunk;

    unsigned long long acc[8][2];
    #pragma unroll
    for (int oc = 0; oc < 8; ++oc) { acc[oc][0] = 0ull; acc[oc][1] = 0ull; }

    for (int c = cbeg; c < cend; ++c) {
        const float* sc = src + (((size_t)b * srcC + coff + c) << 12);
        const float* wc = wt + (size_t)c * KK * O;
        __syncthreads();
        for (int idx = tid; idx < ROWS_X * WPAD; idx += 256) {
            const int rr  = idx / WPAD;
            const int s   = idx - rr * WPAD;
            const int yy  = h0 - PAD + rr;
            const int col = s - PAD;
            float v = 0.f;
            if ((unsigned)yy < 64u && (unsigned)col < 64u) v = sc[yy * 64 + col];
            XS[rr][s] = v;
        }
        for (int idx = tid; idx < KK * 32; idx += 256) {
            const int tap = idx >> 5;
            const int oc  = idx & 31;
            const int o   = o0 + oc;
            const float w = (o < O) ? wc[tap * O + o] : 0.f;
            WS2[tap][oc] = make_float2(w, w);
        }
        __syncthreads();

        #pragma unroll 1
        for (int i = 0; i < K; ++i) {
            const int ri = i * DIL;
            #pragma unroll
            for (int j = 0; j < K; ++j) {
                const ulonglong2* wrow = (const ulonglong2*)&WS2[i * K + j][og * 8];
                const ulonglong2 wq0 = wrow[0];
                const ulonglong2 wq1 = wrow[1];
                const ulonglong2 wq2 = wrow[2];
                const ulonglong2 wq3 = wrow[3];
                const int sx = lane + j * DIL;
                const unsigned long long xa = pk2(XS[ri + 0][sx], XS[ri + 1][sx]);
                const unsigned long long xb = pk2(XS[ri + 2][sx], XS[ri + 3][sx]);
                fma2(acc[0][0], wq0.x, xa);  fma2(acc[0][1], wq0.x, xb);
                fma2(acc[1][0], wq0.y, xa);  fma2(acc[1][1], wq0.y, xb);
                fma2(acc[2][0], wq1.x, xa);  fma2(acc[2][1], wq1.x, xb);
                fma2(acc[3][0], wq1.y, xa);  fma2(acc[3][1], wq1.y, xb);
                fma2(acc[4][0], wq2.x, xa);  fma2(acc[4][1], wq2.x, xb);
                fma2(acc[5][0], wq2.y, xa);  fma2(acc[5][1], wq2.y, xb);
                fma2(acc[6][0], wq3.x, xa);  fma2(acc[6][1], wq3.x, xb);
                fma2(acc[7][0], wq3.y, xa);  fma2(acc[7][1], wq3.y, xb);
            }
        }
    }

    float* pb = part + (((size_t)sp * 2 + b) * O) * HWSZ;
    #pragma unroll
    for (int oc = 0; oc < 8; ++oc) {
        const int o = o0 + og * 8 + oc;
        if (o < O) {
            float r0, r1, r2, r3;
            unpk2(acc[oc][0], r0, r1);
            unpk2(acc[oc][1], r2, r3);
            float* po = pb + (size_t)o * HWSZ + h0 * 64 + lane;
            po[0]   = r0;
            po[64]  = r1;
            po[128] = r2;
            po[192] = r3;
        }
    }
}

// combine: out[b,o,p] = bias[o] + sum_sp part[sp][b][o][p]   (float4)
__global__ void combine_kernel(const float* __restrict__ part,
                               const float* __restrict__ bias,
                               int O, int ns, float* __restrict__ out)
{
    const int p = blockIdx.x * 256 + threadIdx.x;
    const int o = blockIdx.y;
    const int b = blockIdx.z;
    const float bs = bias[o];
    float4 s = make_float4(bs, bs, bs, bs);
    for (int sp = 0; sp < ns; ++sp) {
        const float4 v = ((const float4*)part)[(((size_t)sp * 2 + b) * O + o) * 1024 + p];
        s.x += v.x; s.y += v.y; s.z += v.z; s.w += v.w;
    }
    ((float4*)out)[((size_t)b * O + o) * 1024 + p] = s;
}

// ---------------------------------------------------------------------------
// Deformable depthwise conv: index math once per tap, applied to 4 channels.
// Block 256 thr (4 rows x 64 cols); grid (16, 16 cgroups, 2) = 512 blocks.
// ---------------------------------------------------------------------------
template<int KS, int DIL, int PAD>
__global__ void deform_kernel(const float* __restrict__ src, int srcC, int coff,
                              const float* __restrict__ off,
                              const float* __restrict__ dw,
                              float* __restrict__ out)
{
    constexpr int K = KS * KS;
    __shared__ float sdw[4][K];

    const int tid = threadIdx.x;
    const int w   = tid & 63;
    const int r   = tid >> 6;
    const int h   = blockIdx.x * 4 + r;
    const int cg  = blockIdx.y;
    const int b   = blockIdx.z;

    if (tid < 4 * K) sdw[tid / K][tid % K] = dw[(cg * 4 + tid / K) * K + tid % K];
    __syncthreads();

    const float* xb = src + ((size_t)b * srcC + coff + cg * 4) * HWSZ;
    const float* ob = off + (size_t)b * (2 * K) * HWSZ + h * WW + w;

    float acc[4];
    #pragma unroll
    for (int c = 0; c < 4; ++c) acc[c] = 0.f;

    #pragma unroll 1
    for (int kidx = 0; kidx < K; ++kidx) {
        const float oy = ob[(2 * kidx)     * HWSZ];
        const float ox = ob[(2 * kidx + 1) * HWSZ];
        const float py = oy + (float)(h - PAD + (kidx / KS) * DIL);
        const float px = ox + (float)(w - PAD + (kidx % KS) * DIL);
        const int   y0 = __float2int_rd(py);
        const int   x0 = __float2int_rd(px);
        const float ly = py - (float)y0;
        const float lx = px - (float)x0;
        const float hy = 1.f - ly;
        const float hx = 1.f - lx;

        const float m_y0 = ((unsigned)y0       < 64u) ? 1.f : 0.f;
        const float m_y1 = ((unsigned)(y0 + 1) < 64u) ? 1.f : 0.f;
        const float m_x0 = ((unsigned)x0       < 64u) ? 1.f : 0.f;
        const float m_x1 = ((unsigned)(x0 + 1) < 64u) ? 1.f : 0.f;

        const int yc0 = min(max(y0, 0), 63);
        const int yc1 = min(max(y0 + 1, 0), 63);
        const int xc0 = min(max(x0, 0), 63);
        const int xc1 = min(max(x0 + 1, 0), 63);

        const int i00 = yc0 * 64 + xc0;
        const int i01 = yc0 * 64 + xc1;
        const int i10 = yc1 * 64 + xc0;
        const int i11 = yc1 * 64 + xc1;

        const float w00 = hy * hx * (m_y0 * m_x0);
        const float w01 = hy * lx * (m_y0 * m_x1);
        const float w10 = ly * hx * (m_y1 * m_x0);
        const float w11 = ly * lx * (m_y1 * m_x1);

        #pragma unroll
        for (int c = 0; c < 4; ++c) {
            const float* xc = xb + c * HWSZ;
            float v = xc[i00] * w00;
            v = fmaf(xc[i01], w01, v);
            v = fmaf(xc[i10], w10, v);
            v = fmaf(xc[i11], w11, v);
            acc[c] = fmaf(v, sdw[c][kidx], acc[c]);
        }
    }

    #pragma unroll
    for (int c = 0; c < 4; ++c)
        out[((size_t)b * CCH + cg * 4 + c) * HWSZ + h * WW + w] = acc[c];
}

// ---------------------------------------------------------------------------
// 1x1 conv fused with gating, f32x2: each thread = 2 adjacent pixels.
// ---------------------------------------------------------------------------
__global__ void conv1x1_gate_kernel(const float* __restrict__ in,
                                    const float* __restrict__ wv,
                                    const float* __restrict__ bias,
                                    const float* __restrict__ x,
                                    int xcoff, float* __restrict__ out)
{
    __shared__ float2 wdup[CCH];
    const int tid = threadIdx.x;
    const int o   = blockIdx.y;
    const int b   = blockIdx.z;
    const int px0 = blockIdx.x * 512 + tid * 2;

    if (tid < CCH) {
        const float wv_ = wv[o * CCH + tid];
        wdup[tid] = make_float2(wv_, wv_);
    }
    __syncthreads();

    const float bs = bias[o];
    unsigned long long acc = pk2(bs, bs);
    const char* ib = (const char*)(in + (size_t)b * CCH * HWSZ + px0);
    #pragma unroll
    for (int c = 0; c < CCH; ++c) {
        const unsigned long long iv = *(const unsigned long long*)(ib + (size_t)c * (HWSZ * 4));
        const unsigned long long wq = *(const unsigned long long*)&wdup[c];
        fma2(acc, wq, iv);
    }

    const size_t oi = ((size_t)b * 128 + xcoff + o) * HWSZ + px0;
    const unsigned long long xv = *(const unsigned long long*)(x + oi);
    *(unsigned long long*)(out + oi) = mul2(acc, xv);
}

// ---------------------------------------------------------------------------
extern "C" void kernel_launch(void* const* d_in, const int* in_sizes, int n_in,
                              void* d_out, int out_size)
{
    const float* x          = (const float*)d_in[0];
    const float* cv0_off_w  = (const float*)d_in[1];
    const float* cv0_off_b  = (const float*)d_in[2];
    const float* cv0_w      = (const float*)d_in[3];
    const float* cvs_off_w  = (const float*)d_in[4];
    const float* cvs_off_b  = (const float*)d_in[5];
    const float* cvs_w      = (const float*)d_in[6];
    const float* c0_off_w   = (const float*)d_in[7];
    const float* c0_off_b   = (const float*)d_in[8];
    const float* c0_w       = (const float*)d_in[9];
    const float* cs_off_w   = (const float*)d_in[10];
    const float* cs_off_b   = (const float*)d_in[11];
    const float* cs_w       = (const float*)d_in[12];
    const float* conv1_w    = (const float*)d_in[13];
    const float* conv1_b    = (const float*)d_in[14];
    const float* conv2_w    = (const float*)d_in[15];
    const float* conv2_b    = (const float*)d_in[16];
    float* out = (float*)d_out;

    static cudaStream_t s2 = nullptr;
    static cudaEvent_t evRoot = nullptr, evJoin = nullptr;
    if (!s2) {
        cudaStreamCreateWithFlags(&s2, cudaStreamNonBlocking);
        cudaEventCreateWithFlags(&evRoot, cudaEventDisableTiming);
        cudaEventCreateWithFlags(&evJoin, cudaEventDisableTiming);
    }

    float *offb, *tmp, *part, *wt;
    cudaGetSymbolAddress((void**)&offb, g_off);
    cudaGetSymbolAddress((void**)&tmp,  g_tmp);
    cudaGetSymbolAddress((void**)&part, g_part);
    cudaGetSymbolAddress((void**)&wt,   g_wt);

    float* off0  = offb;                             // branch0 offsets (<=100 ch)
    float* off1  = offb + (size_t)2 * 100 * HWSZ;    // branch1 offsets (<=196 ch)
    float* t0a   = tmp;
    float* t1a   = tmp + (size_t)1 * CCH * 2 * HWSZ;
    float* t0b   = tmp + (size_t)2 * CCH * 2 * HWSZ;
    float* t1b   = tmp + (size_t)3 * CCH * 2 * HWSZ;
    float* part0 = part;
    float* part1 = part + (size_t)4 * 1024 * 1024;

    const int taps3 = 576, taps5 = 1600, taps7 = 3136;
    float* wt_cv0 = wt;
    float* wt_cvs = wt_cv0 + 18 * taps3;
    float* wt_c0  = wt_cvs + 50 * taps5;
    float* wt_cs  = wt_c0  + 50 * taps5;

    dim3 b256(256);
    const int n_all = 18 * taps3 + 50 * taps5 + 50 * taps5 + 98 * taps7;
    wtrans_all<<<(n_all + 255) / 256, b256>>>(cv0_off_w, cvs_off_w, c0_off_w, cs_off_w, wt);

    // fork: branch1 runs on s2
    cudaEventRecord(evRoot, 0);
    cudaStreamWaitEvent(s2, evRoot, 0);

    // ---- Branch 0 (stream 0): channels [0,64) ----
    offconv_gemm<3,1,1><<<dim3(16, 1, 2 * 16), b256>>>(x, 128, 0, wt_cv0, 18, 16, part0);
    combine_kernel<<<dim3(4, 18, 2), b256>>>(part0, cv0_off_b, 18, 16, off0);
    deform_kernel<3,1,1><<<dim3(16, 16, 2), b256>>>(x, 128, 0, off0, cv0_w, t0a);

    offconv_gemm<5,3,6><<<dim3(16, 2, 2 * 8), b256>>>(t0a, 64, 0, wt_cvs, 50, 8, part0);
    combine_kernel<<<dim3(4, 50, 2), b256>>>(part0, cvs_off_b, 50, 8, off0);
    deform_kernel<5,3,6><<<dim3(16, 16, 2), b256>>>(t0a, 64, 0, off0, cvs_w, t1a);

    conv1x1_gate_kernel<<<dim3(8, 64, 2), b256>>>(t1a, conv1_w, conv1_b, x, 0, out);

    // ---- Branch 1 (stream s2): channels [64,128) ----
    offconv_gemm<5,1,2><<<dim3(16, 2, 2 * 8), b256, 0, s2>>>(x, 128, 64, wt_c0, 50, 8, part1);
    combine_kernel<<<dim3(4, 50, 2), b256, 0, s2>>>(part1, c0_off_b, 50, 8, off1);
    deform_kernel<5,1,2><<<dim3(16, 16, 2), b256, 0, s2>>>(x, 128, 64, off1, c0_w, t0b);

    offconv_gemm<7,3,9><<<dim3(16, 4, 2 * 4), b256, 0, s2>>>(t0b, 64, 0, wt_cs, 98, 4, part1);
    combine_kernel<<<dim3(4, 98, 2), b256, 0, s2>>>(part1, cs_off_b, 98, 4, off1);
    deform_kernel<7,3,9><<<dim3(16, 16, 2), b256, 0, s2>>>(t0b, 64, 0, off1, cs_w, t1b);

    conv1x1_gate_kernel<<<dim3(8, 64, 2), b256, 0, s2>>>(t1b, conv2_w, conv2_b, x, 64, out);

    // join
    cudaEventRecord(evJoin, s2);
    cudaStreamWaitEvent(0, evJoin, 0);
}